// round 1
// baseline (speedup 1.0000x reference)
#include <cuda_runtime.h>

// ---------------------------------------------------------------------------
// IPB windowed inhibition attention, fp32.
// x: (1, 8, 256, 256, 28). WS=8 -> 32x32 windows, n=64 tokens, 8192 (win,B)
// independent attention problems. One CTA per (win,B).
// ---------------------------------------------------------------------------

#define TPB 256

namespace {
constexpr int H_STR = 256 * 28;        // 7168
constexpr int B_STR = 256 * 256 * 28;  // 1835008
// smem layout (floats): sx,sq,sk,sv [64*29] | ssim [64*65] | Wqk [56*29]
// | Wv [28*29] | Wout [28*29] | sigq[64] sigk[64] sth[64] sred[2]
constexpr int SM_FLOATS = 4 * 64 * 29 + 64 * 65 + 56 * 29 + 2 * 28 * 29 + 3 * 64 + 2;
constexpr int SM_BYTES  = SM_FLOATS * 4;  // 60104
}

__global__ void __launch_bounds__(TPB) ipb_kernel(
    const float* __restrict__ x,
    const float* __restrict__ W_qk,   // [56,28]
    const float* __restrict__ W_v,    // [28,28]
    const float* __restrict__ W_out,  // [28,28]
    const float* __restrict__ b_out,  // [28]
    const float* __restrict__ W_pcq,  // [1,28]
    const float* __restrict__ b_pcq,  // [1]
    const float* __restrict__ W_pck,  // [1,28]
    const float* __restrict__ b_pck,  // [1]
    const float* __restrict__ W_m1,   // [1,64]
    const float* __restrict__ W_m2a,  // [64,64]
    const float* __restrict__ W_m2b,  // [1,64]
    float* __restrict__ out)
{
    extern __shared__ float sm[];
    float* sx   = sm;                 // 64*29  (reused as o1 after PV)
    float* sq   = sx   + 64 * 29;
    float* sk   = sq   + 64 * 29;
    float* sv   = sk   + 64 * 29;
    float* ssim = sv   + 64 * 29;     // 64*65
    float* sWqk = ssim + 64 * 65;     // 56*29
    float* sWv  = sWqk + 56 * 29;     // 28*29
    float* sWo  = sWv  + 28 * 29;     // 28*29
    float* sigq = sWo  + 28 * 29;     // 64
    float* sigk = sigq + 64;          // 64
    float* sth  = sigk + 64;          // 64
    float* sred = sth  + 64;          // 2

    const int tid  = threadIdx.x;
    const int widx = blockIdx.x & 1023;   // window index (adjacent blocks -> adjacent windows)
    const int Bi   = blockIdx.x >> 10;    // batch plane
    const int wh = widx >> 5, ww = widx & 31;
    const float* xbase = x + (size_t)Bi * B_STR + wh * 8 * H_STR + ww * 8 * 28;

    // ---- load weights + x tile into smem (padded stride 29) ----
    for (int i = tid; i < 56 * 28; i += TPB)
        sWqk[(i / 28) * 29 + (i % 28)] = W_qk[i];
    for (int i = tid; i < 28 * 28; i += TPB) {
        sWv[(i / 28) * 29 + (i % 28)] = W_v[i];
        sWo[(i / 28) * 29 + (i % 28)] = W_out[i];
    }
    for (int i = tid; i < 64 * 28; i += TPB) {
        int r = i / 28, cc = i - r * 28;
        sx[r * 29 + cc] = xbase[(r >> 3) * H_STR + (r & 7) * 28 + cc];
    }
    __syncthreads();

    // ---- fused QKV projection: out[64 x 84] = sx[64x28] @ [Wqk|Wv]^T ----
    // 4x4 register tiles -> 16*21 = 336 units
    for (int u = tid; u < 336; u += TPB) {
        const int r4 = (u / 21) * 4;
        const int c4 = (u % 21) * 4;
        const float* wb = (c4 < 56) ? (sWqk + c4 * 29) : (sWv + (c4 - 56) * 29);
        float acc[4][4] = {};
        #pragma unroll 4
        for (int kk = 0; kk < 28; kk++) {
            float a[4], w[4];
            #pragma unroll
            for (int t = 0; t < 4; t++) a[t] = sx[(r4 + t) * 29 + kk];
            #pragma unroll
            for (int t = 0; t < 4; t++) w[t] = wb[t * 29 + kk];
            #pragma unroll
            for (int rr = 0; rr < 4; rr++)
                #pragma unroll
                for (int mm = 0; mm < 4; mm++)
                    acc[rr][mm] = fmaf(a[rr], w[mm], acc[rr][mm]);
        }
        float* dst; int cc;
        if (c4 < 28)      { dst = sq; cc = c4; }
        else if (c4 < 56) { dst = sk; cc = c4 - 28; }
        else              { dst = sv; cc = c4 - 56; }
        #pragma unroll
        for (int rr = 0; rr < 4; rr++)
            #pragma unroll
            for (int mm = 0; mm < 4; mm++)
                dst[(r4 + rr) * 29 + cc + mm] = acc[rr][mm];
    }
    __syncthreads();

    // ---- per-token sigma (128 threads) ----
    if (tid < 128) {
        const int i = tid & 63;
        const float* row = (tid < 64) ? (sq + i * 29) : (sk + i * 29);
        const float* wp  = (tid < 64) ? W_pcq : W_pck;
        float acc = (tid < 64) ? b_pcq[0] : b_pck[0];
        #pragma unroll 7
        for (int kk = 0; kk < 28; kk++) acc = fmaf(row[kk], wp[kk], acc);
        ((tid < 64) ? sigq : sigk)[i] = acc;
    }

    // ---- sim = Q @ K^T : 4x4 tiles, exactly 256 units ----
    {
        const int r4 = (tid >> 4) * 4;
        const int j4 = (tid & 15) * 4;
        float acc[4][4] = {};
        #pragma unroll 4
        for (int kk = 0; kk < 28; kk++) {
            float a[4], b[4];
            #pragma unroll
            for (int t = 0; t < 4; t++) a[t] = sq[(r4 + t) * 29 + kk];
            #pragma unroll
            for (int t = 0; t < 4; t++) b[t] = sk[(j4 + t) * 29 + kk];
            #pragma unroll
            for (int rr = 0; rr < 4; rr++)
                #pragma unroll
                for (int mm = 0; mm < 4; mm++)
                    acc[rr][mm] = fmaf(a[rr], b[mm], acc[rr][mm]);
        }
        #pragma unroll
        for (int rr = 0; rr < 4; rr++)
            #pragma unroll
            for (int mm = 0; mm < 4; mm++)
                ssim[(r4 + rr) * 65 + j4 + mm] = acc[rr][mm];
    }
    __syncthreads();

    // ---- theta_raw[i] = sum_{j!=i} sim[i,j] * W_m1[j] ----
    if (tid < 64) {
        float acc = 0.f;
        const float* srow = ssim + tid * 65;
        #pragma unroll 8
        for (int j = 0; j < 64; j++) acc = fmaf(srow[j], W_m1[j], acc);
        acc -= srow[tid] * W_m1[tid];
        sth[tid] = acc;
    }
    __syncthreads();

    // ---- t = LeakyReLU(theta_raw @ W_m2a^T), theta = t . W_m2b ----
    if (tid < 64) {
        float acc = 0.f;
        const float* wrow = W_m2a + tid * 64;
        #pragma unroll 8
        for (int j = 0; j < 64; j++) acc = fmaf(sth[j], wrow[j], acc);
        acc = (acc >= 0.f) ? acc : 0.1f * acc;
        float val = acc * W_m2b[tid];
        #pragma unroll
        for (int o = 16; o > 0; o >>= 1)
            val += __shfl_down_sync(0xffffffffu, val, o);
        if ((tid & 31) == 0) sred[tid >> 5] = val;
    }
    __syncthreads();
    const float theta = sred[0] + sred[1];

    // ---- scale by Sigma, softmax, threshold mask (1 warp / row) ----
    {
        const int lane = tid & 31, wrp = tid >> 5;
        #pragma unroll
        for (int it = 0; it < 8; it++) {
            const int r = it * 8 + wrp;
            float* srow = ssim + r * 65;
            const float sgq = sigq[r];
            float s0 = srow[lane]      * (sgq * sigk[lane]);
            float s1 = srow[lane + 32] * (sgq * sigk[lane + 32]);
            float m = fmaxf(s0, s1);
            #pragma unroll
            for (int o = 16; o > 0; o >>= 1)
                m = fmaxf(m, __shfl_xor_sync(0xffffffffu, m, o));
            float e0 = __expf(s0 - m), e1 = __expf(s1 - m);
            float ss = e0 + e1;
            #pragma unroll
            for (int o = 16; o > 0; o >>= 1)
                ss += __shfl_xor_sync(0xffffffffu, ss, o);
            const float inv = 1.0f / ss;
            srow[lane]      = (s0 > theta) ? e0 * inv : 0.f;
            srow[lane + 32] = (s1 > theta) ? e1 * inv : 0.f;
        }
    }
    __syncthreads();

    // ---- o1 = attn @ V : 2x4 tiles, 32*7 = 224 units; write into sx ----
    if (tid < 224) {
        const int r2 = (tid / 7) * 2;
        const int d4 = (tid % 7) * 4;
        float acc[2][4] = {};
        #pragma unroll 4
        for (int j = 0; j < 64; j++) {
            const float a0 = ssim[r2 * 65 + j];
            const float a1 = ssim[(r2 + 1) * 65 + j];
            #pragma unroll
            for (int mm = 0; mm < 4; mm++) {
                const float vv = sv[j * 29 + d4 + mm];
                acc[0][mm] = fmaf(a0, vv, acc[0][mm]);
                acc[1][mm] = fmaf(a1, vv, acc[1][mm]);
            }
        }
        #pragma unroll
        for (int rr = 0; rr < 2; rr++)
            #pragma unroll
            for (int mm = 0; mm < 4; mm++)
                sx[(r2 + rr) * 29 + d4 + mm] = acc[rr][mm];
    }
    __syncthreads();

    // ---- final = o1 @ W_out^T + b_out, scatter with un-window map ----
    if (tid < 224) {
        const int r2 = (tid / 7) * 2;
        const int d4 = (tid % 7) * 4;
        float acc[2][4];
        #pragma unroll
        for (int mm = 0; mm < 4; mm++) {
            const float bb = b_out[d4 + mm];
            acc[0][mm] = bb; acc[1][mm] = bb;
        }
        #pragma unroll 7
        for (int e = 0; e < 28; e++) {
            const float o0 = sx[r2 * 29 + e];
            const float o1 = sx[(r2 + 1) * 29 + e];
            #pragma unroll
            for (int mm = 0; mm < 4; mm++) {
                const float wv = sWo[(d4 + mm) * 29 + e];
                acc[0][mm] = fmaf(o0, wv, acc[0][mm]);
                acc[1][mm] = fmaf(o1, wv, acc[1][mm]);
            }
        }
        #pragma unroll
        for (int rr = 0; rr < 2; rr++) {
            const int r = r2 + rr;
            float* ob = out + (size_t)Bi * B_STR + (wh * 8 + (r >> 3)) * H_STR
                        + (ww * 8 + (r & 7)) * 28 + d4;
            #pragma unroll
            for (int mm = 0; mm < 4; mm++) ob[mm] = acc[rr][mm];
        }
    }
}

extern "C" void kernel_launch(void* const* d_in, const int* in_sizes, int n_in,
                              void* d_out, int out_size) {
    (void)in_sizes; (void)n_in; (void)out_size;
    cudaFuncSetAttribute(ipb_kernel, cudaFuncAttributeMaxDynamicSharedMemorySize, SM_BYTES);
    ipb_kernel<<<8192, TPB, SM_BYTES>>>(
        (const float*)d_in[0],   // x
        (const float*)d_in[1],   // W_qk
        (const float*)d_in[2],   // W_v
        (const float*)d_in[3],   // W_out
        (const float*)d_in[4],   // b_out
        (const float*)d_in[5],   // W_pcq
        (const float*)d_in[6],   // b_pcq
        (const float*)d_in[7],   // W_pck
        (const float*)d_in[8],   // b_pck
        (const float*)d_in[9],   // W_m1
        (const float*)d_in[10],  // W_m2a
        (const float*)d_in[11],  // W_m2b
        (float*)d_out);
}

// round 2
// speedup vs baseline: 1.2751x; 1.2751x over previous
#include <cuda_runtime.h>

// ---------------------------------------------------------------------------
// IPB windowed inhibition attention, fp32, float4-vectorized smem pipeline.
// x: (1, 8, 256, 256, 28). WS=8 -> 32x32 windows, n=64 tokens, 8192 (win,B)
// independent attention problems. One CTA per (win,B).
// ---------------------------------------------------------------------------

#define TPB 256

namespace {
constexpr int H_STR = 256 * 28;        // 7168
constexpr int B_STR = 256 * 256 * 28;  // 1835008

// smem float offsets
constexpr int OFF_XT   = 0;                    // [28][64] x transposed (reused as o1 [64][28])
constexpr int OFF_QT   = OFF_XT   + 28 * 64;   // [28][64] swizzled
constexpr int OFF_KT   = OFF_QT   + 28 * 64;   // [28][64] swizzled
constexpr int OFF_V    = OFF_KT   + 28 * 64;   // [64][28] row-major
constexpr int OFF_SIM  = OFF_V    + 64 * 28;   // [64][68]
constexpr int OFF_WT   = OFF_SIM  + 64 * 68;   // [28][96] (W_qk|W_v transposed)
constexpr int OFF_WO   = OFF_WT   + 28 * 96;   // [28][28] row-major
constexpr int OFF_SGQ  = OFF_WO   + 28 * 28;   // 64
constexpr int OFF_SGK  = OFF_SGQ  + 64;        // 64
constexpr int OFF_TH   = OFF_SGK  + 64;        // 64
constexpr int OFF_RED  = OFF_TH   + 64;        // 2
constexpr int SM_FLOATS = OFF_RED + 4;
constexpr int SM_BYTES  = SM_FLOATS * 4;       // ~60.8 KB -> 3 CTAs/SM

// swizzled float4-chunk offset for transposed Q/K: element (k, r)
__device__ __forceinline__ int swz4(int k, int r4) {
    return k * 64 + ((((r4 >> 2) ^ (k & 15)) << 2));
}
__device__ __forceinline__ int swz1(int k, int r) {
    return k * 64 + (((((r >> 2) ^ (k & 15)) << 2)) | (r & 3));
}
}

__global__ void __launch_bounds__(TPB) ipb_kernel(
    const float* __restrict__ x,
    const float* __restrict__ W_qk,   // [56,28]
    const float* __restrict__ W_v,    // [28,28]
    const float* __restrict__ W_out,  // [28,28]
    const float* __restrict__ b_out,  // [28]
    const float* __restrict__ W_pcq,  // [1,28]
    const float* __restrict__ b_pcq,  // [1]
    const float* __restrict__ W_pck,  // [1,28]
    const float* __restrict__ b_pck,  // [1]
    const float* __restrict__ W_m1,   // [1,64]
    const float* __restrict__ W_m2a,  // [64,64]
    const float* __restrict__ W_m2b,  // [1,64]
    float* __restrict__ out)
{
    extern __shared__ float sm[];
    float* sxT  = sm + OFF_XT;
    float* sqT  = sm + OFF_QT;
    float* skT  = sm + OFF_KT;
    float* sv   = sm + OFF_V;
    float* ssim = sm + OFF_SIM;
    float* sWT  = sm + OFF_WT;
    float* sWo  = sm + OFF_WO;
    float* sigq = sm + OFF_SGQ;
    float* sigk = sm + OFF_SGK;
    float* sth  = sm + OFF_TH;
    float* sred = sm + OFF_RED;

    const int tid  = threadIdx.x;
    const int widx = blockIdx.x & 1023;
    const int Bi   = blockIdx.x >> 10;
    const int wh = widx >> 5, ww = widx & 31;
    const float* xbase = x + (size_t)Bi * B_STR + wh * 8 * H_STR + ww * 8 * 28;

    // ---- stage 0: load x (transposed), W_qk|W_v (transposed), W_out ----
    for (int i = tid; i < 448; i += TPB) {           // 64 tokens * 7 float4
        const int r = i / 7, c4 = (i % 7) * 4;
        const float4 v = *(const float4*)(xbase + (r >> 3) * H_STR + (r & 7) * 28 + c4);
        sxT[(c4 + 0) * 64 + r] = v.x;
        sxT[(c4 + 1) * 64 + r] = v.y;
        sxT[(c4 + 2) * 64 + r] = v.z;
        sxT[(c4 + 3) * 64 + r] = v.w;
    }
    for (int i = tid; i < 588; i += TPB) {           // 84 cols * 7 float4
        const int c = i / 7, k4 = (i % 7) * 4;
        const float4 v = (c < 56) ? *(const float4*)(W_qk + c * 28 + k4)
                                  : *(const float4*)(W_v + (c - 56) * 28 + k4);
        sWT[(k4 + 0) * 96 + c] = v.x;
        sWT[(k4 + 1) * 96 + c] = v.y;
        sWT[(k4 + 2) * 96 + c] = v.z;
        sWT[(k4 + 3) * 96 + c] = v.w;
    }
    for (int i = tid; i < 196; i += TPB)
        ((float4*)sWo)[i] = ((const float4*)W_out)[i];
    __syncthreads();

    // ---- stage 1: QKV projection out[64 x 84] = x @ [Wqk|Wv]^T ----
    for (int u = tid; u < 336; u += TPB) {
        const int r4 = (u / 21) * 4;
        const int c4 = (u % 21) * 4;
        float4 acc0 = {0,0,0,0}, acc1 = {0,0,0,0}, acc2 = {0,0,0,0}, acc3 = {0,0,0,0};
        #pragma unroll 4
        for (int kk = 0; kk < 28; kk++) {
            const float4 a = *(const float4*)&sxT[kk * 64 + r4];   // 4 tokens
            const float4 w = *(const float4*)&sWT[kk * 96 + c4];   // 4 out-cols
            acc0.x = fmaf(a.x, w.x, acc0.x); acc0.y = fmaf(a.x, w.y, acc0.y);
            acc0.z = fmaf(a.x, w.z, acc0.z); acc0.w = fmaf(a.x, w.w, acc0.w);
            acc1.x = fmaf(a.y, w.x, acc1.x); acc1.y = fmaf(a.y, w.y, acc1.y);
            acc1.z = fmaf(a.y, w.z, acc1.z); acc1.w = fmaf(a.y, w.w, acc1.w);
            acc2.x = fmaf(a.z, w.x, acc2.x); acc2.y = fmaf(a.z, w.y, acc2.y);
            acc2.z = fmaf(a.z, w.z, acc2.z); acc2.w = fmaf(a.z, w.w, acc2.w);
            acc3.x = fmaf(a.w, w.x, acc3.x); acc3.y = fmaf(a.w, w.y, acc3.y);
            acc3.z = fmaf(a.w, w.z, acc3.z); acc3.w = fmaf(a.w, w.w, acc3.w);
        }
        const float accr[4][4] = {
            {acc0.x, acc1.x, acc2.x, acc3.x},   // col c4+0, tokens r4..r4+3
            {acc0.y, acc1.y, acc2.y, acc3.y},
            {acc0.z, acc1.z, acc2.z, acc3.z},
            {acc0.w, acc1.w, acc2.w, acc3.w}};
        if (c4 < 56) {
            float* dst = (c4 < 28) ? sqT : skT;
            const int cb = (c4 < 28) ? c4 : c4 - 28;
            #pragma unroll
            for (int mm = 0; mm < 4; mm++) {
                const int row = cb + mm;
                *(float4*)&dst[swz4(row, r4)] =
                    make_float4(accr[mm][0], accr[mm][1], accr[mm][2], accr[mm][3]);
            }
        } else {
            const int d0 = c4 - 56;
            #pragma unroll
            for (int rr = 0; rr < 4; rr++)
                *(float4*)&sv[(r4 + rr) * 28 + d0] =
                    make_float4(accr[0][rr], accr[1][rr], accr[2][rr], accr[3][rr]);
        }
    }
    __syncthreads();

    // ---- stage 2a: per-token sigma (128 threads) ----
    if (tid < 128) {
        const int i = tid & 63;
        const float* T  = (tid < 64) ? sqT : skT;
        const float* wp = (tid < 64) ? W_pcq : W_pck;
        float acc = (tid < 64) ? b_pcq[0] : b_pck[0];
        #pragma unroll 7
        for (int c = 0; c < 28; c++)
            acc = fmaf(T[swz1(c, i)], wp[c], acc);
        ((tid < 64) ? sigq : sigk)[i] = acc;
    }

    // ---- stage 2b: sim = Q @ K^T (4x4 tiles, 256 units) ----
    {
        const int r4 = (tid >> 4) * 4;
        const int j4 = (tid & 15) * 4;
        float4 acc0 = {0,0,0,0}, acc1 = {0,0,0,0}, acc2 = {0,0,0,0}, acc3 = {0,0,0,0};
        #pragma unroll 4
        for (int kk = 0; kk < 28; kk++) {
            const float4 a = *(const float4*)&sqT[swz4(kk, r4)];
            const float4 b = *(const float4*)&skT[swz4(kk, j4)];
            acc0.x = fmaf(a.x, b.x, acc0.x); acc0.y = fmaf(a.x, b.y, acc0.y);
            acc0.z = fmaf(a.x, b.z, acc0.z); acc0.w = fmaf(a.x, b.w, acc0.w);
            acc1.x = fmaf(a.y, b.x, acc1.x); acc1.y = fmaf(a.y, b.y, acc1.y);
            acc1.z = fmaf(a.y, b.z, acc1.z); acc1.w = fmaf(a.y, b.w, acc1.w);
            acc2.x = fmaf(a.z, b.x, acc2.x); acc2.y = fmaf(a.z, b.y, acc2.y);
            acc2.z = fmaf(a.z, b.z, acc2.z); acc2.w = fmaf(a.z, b.w, acc2.w);
            acc3.x = fmaf(a.w, b.x, acc3.x); acc3.y = fmaf(a.w, b.y, acc3.y);
            acc3.z = fmaf(a.w, b.z, acc3.z); acc3.w = fmaf(a.w, b.w, acc3.w);
        }
        *(float4*)&ssim[(r4 + 0) * 68 + j4] = acc0;
        *(float4*)&ssim[(r4 + 1) * 68 + j4] = acc1;
        *(float4*)&ssim[(r4 + 2) * 68 + j4] = acc2;
        *(float4*)&ssim[(r4 + 3) * 68 + j4] = acc3;
    }
    __syncthreads();

    // ---- stage 3: theta_raw[i] = sum_{j!=i} sim[i,j] * W_m1[j] ----
    if (tid < 64) {
        const float* srow = ssim + tid * 68;
        float acc = 0.f;
        #pragma unroll
        for (int j4 = 0; j4 < 64; j4 += 4) {
            const float4 s = *(const float4*)&srow[j4];
            const float4 w = *(const float4*)&W_m1[j4];
            acc = fmaf(s.x, w.x, acc); acc = fmaf(s.y, w.y, acc);
            acc = fmaf(s.z, w.z, acc); acc = fmaf(s.w, w.w, acc);
        }
        acc -= srow[tid] * W_m1[tid];
        sth[tid] = acc;
    }
    __syncthreads();

    // ---- stage 4: t = LeakyReLU(theta @ W_m2a^T); theta = t . W_m2b ----
    if (tid < 64) {
        const float* wrow = W_m2a + tid * 64;
        float acc = 0.f;
        #pragma unroll
        for (int j4 = 0; j4 < 64; j4 += 4) {
            const float4 t = *(const float4*)&sth[j4];
            const float4 w = *(const float4*)&wrow[j4];
            acc = fmaf(t.x, w.x, acc); acc = fmaf(t.y, w.y, acc);
            acc = fmaf(t.z, w.z, acc); acc = fmaf(t.w, w.w, acc);
        }
        acc = (acc >= 0.f) ? acc : 0.1f * acc;
        float val = acc * W_m2b[tid];
        #pragma unroll
        for (int o = 16; o > 0; o >>= 1)
            val += __shfl_down_sync(0xffffffffu, val, o);
        if ((tid & 31) == 0) sred[tid >> 5] = val;
    }
    __syncthreads();
    const float theta = sred[0] + sred[1];

    // ---- stage 5: Sigma scale, softmax, threshold (1 warp / row) ----
    {
        const int lane = tid & 31, wrp = tid >> 5;
        #pragma unroll
        for (int it = 0; it < 8; it++) {
            const int r = it * 8 + wrp;
            float* srow = ssim + r * 68;
            const float sgq = sigq[r];
            float s0 = srow[lane]      * (sgq * sigk[lane]);
            float s1 = srow[lane + 32] * (sgq * sigk[lane + 32]);
            float m = fmaxf(s0, s1);
            #pragma unroll
            for (int o = 16; o > 0; o >>= 1)
                m = fmaxf(m, __shfl_xor_sync(0xffffffffu, m, o));
            float e0 = __expf(s0 - m), e1 = __expf(s1 - m);
            float ss = e0 + e1;
            #pragma unroll
            for (int o = 16; o > 0; o >>= 1)
                ss += __shfl_xor_sync(0xffffffffu, ss, o);
            const float inv = 1.0f / ss;
            srow[lane]      = (s0 > theta) ? e0 * inv : 0.f;
            srow[lane + 32] = (s1 > theta) ? e1 * inv : 0.f;
        }
    }
    __syncthreads();

    // ---- stage 6: o1 = attn @ V (2x4 tiles, 224 units); o1 -> sxT area ----
    float* so = sxT;  // reuse as [64][28] row-major
    if (tid < 224) {
        const int r2 = (tid / 7) * 2;
        const int d4 = (tid % 7) * 4;
        float4 acc0 = {0,0,0,0}, acc1 = {0,0,0,0};
        #pragma unroll 4
        for (int j4 = 0; j4 < 64; j4 += 4) {
            const float4 a0 = *(const float4*)&ssim[r2 * 68 + j4];
            const float4 a1 = *(const float4*)&ssim[(r2 + 1) * 68 + j4];
            {
                const float4 v = *(const float4*)&sv[(j4 + 0) * 28 + d4];
                acc0.x = fmaf(a0.x, v.x, acc0.x); acc0.y = fmaf(a0.x, v.y, acc0.y);
                acc0.z = fmaf(a0.x, v.z, acc0.z); acc0.w = fmaf(a0.x, v.w, acc0.w);
                acc1.x = fmaf(a1.x, v.x, acc1.x); acc1.y = fmaf(a1.x, v.y, acc1.y);
                acc1.z = fmaf(a1.x, v.z, acc1.z); acc1.w = fmaf(a1.x, v.w, acc1.w);
            }
            {
                const float4 v = *(const float4*)&sv[(j4 + 1) * 28 + d4];
                acc0.x = fmaf(a0.y, v.x, acc0.x); acc0.y = fmaf(a0.y, v.y, acc0.y);
                acc0.z = fmaf(a0.y, v.z, acc0.z); acc0.w = fmaf(a0.y, v.w, acc0.w);
                acc1.x = fmaf(a1.y, v.x, acc1.x); acc1.y = fmaf(a1.y, v.y, acc1.y);
                acc1.z = fmaf(a1.y, v.z, acc1.z); acc1.w = fmaf(a1.y, v.w, acc1.w);
            }
            {
                const float4 v = *(const float4*)&sv[(j4 + 2) * 28 + d4];
                acc0.x = fmaf(a0.z, v.x, acc0.x); acc0.y = fmaf(a0.z, v.y, acc0.y);
                acc0.z = fmaf(a0.z, v.z, acc0.z); acc0.w = fmaf(a0.z, v.w, acc0.w);
                acc1.x = fmaf(a1.z, v.x, acc1.x); acc1.y = fmaf(a1.z, v.y, acc1.y);
                acc1.z = fmaf(a1.z, v.z, acc1.z); acc1.w = fmaf(a1.z, v.w, acc1.w);
            }
            {
                const float4 v = *(const float4*)&sv[(j4 + 3) * 28 + d4];
                acc0.x = fmaf(a0.w, v.x, acc0.x); acc0.y = fmaf(a0.w, v.y, acc0.y);
                acc0.z = fmaf(a0.w, v.z, acc0.z); acc0.w = fmaf(a0.w, v.w, acc0.w);
                acc1.x = fmaf(a1.w, v.x, acc1.x); acc1.y = fmaf(a1.w, v.y, acc1.y);
                acc1.z = fmaf(a1.w, v.z, acc1.z); acc1.w = fmaf(a1.w, v.w, acc1.w);
            }
        }
        *(float4*)&so[r2 * 28 + d4]       = acc0;
        *(float4*)&so[(r2 + 1) * 28 + d4] = acc1;
    }
    __syncthreads();

    // ---- stage 7: final = o1 @ W_out^T + b_out, scatter (un-window) ----
    if (tid < 224) {
        const int r2 = (tid / 7) * 2;
        const int c4 = (tid % 7) * 4;
        const float4 bb = *(const float4*)&b_out[c4];
        float4 acc0 = bb, acc1 = bb;
        #pragma unroll
        for (int d4 = 0; d4 < 28; d4 += 4) {
            const float4 o0 = *(const float4*)&so[r2 * 28 + d4];
            const float4 o1 = *(const float4*)&so[(r2 + 1) * 28 + d4];
            {
                const float4 w = *(const float4*)&sWo[(c4 + 0) * 28 + d4];
                acc0.x = fmaf(o0.x, w.x, fmaf(o0.y, w.y, fmaf(o0.z, w.z, fmaf(o0.w, w.w, acc0.x))));
                acc1.x = fmaf(o1.x, w.x, fmaf(o1.y, w.y, fmaf(o1.z, w.z, fmaf(o1.w, w.w, acc1.x))));
            }
            {
                const float4 w = *(const float4*)&sWo[(c4 + 1) * 28 + d4];
                acc0.y = fmaf(o0.x, w.x, fmaf(o0.y, w.y, fmaf(o0.z, w.z, fmaf(o0.w, w.w, acc0.y))));
                acc1.y = fmaf(o1.x, w.x, fmaf(o1.y, w.y, fmaf(o1.z, w.z, fmaf(o1.w, w.w, acc1.y))));
            }
            {
                const float4 w = *(const float4*)&sWo[(c4 + 2) * 28 + d4];
                acc0.z = fmaf(o0.x, w.x, fmaf(o0.y, w.y, fmaf(o0.z, w.z, fmaf(o0.w, w.w, acc0.z))));
                acc1.z = fmaf(o1.x, w.x, fmaf(o1.y, w.y, fmaf(o1.z, w.z, fmaf(o1.w, w.w, acc1.z))));
            }
            {
                const float4 w = *(const float4*)&sWo[(c4 + 3) * 28 + d4];
                acc0.w = fmaf(o0.x, w.x, fmaf(o0.y, w.y, fmaf(o0.z, w.z, fmaf(o0.w, w.w, acc0.w))));
                acc1.w = fmaf(o1.x, w.x, fmaf(o1.y, w.y, fmaf(o1.z, w.z, fmaf(o1.w, w.w, acc1.w))));
            }
        }
        float* ob = out + (size_t)Bi * B_STR + (wh * 8 + (r2 >> 3)) * H_STR
                    + (ww * 8 + (r2 & 7)) * 28 + c4;
        *(float4*)ob = acc0;
        const int r1 = r2 + 1;
        float* ob1 = out + (size_t)Bi * B_STR + (wh * 8 + (r1 >> 3)) * H_STR
                     + (ww * 8 + (r1 & 7)) * 28 + c4;
        *(float4*)ob1 = acc1;
    }
}

extern "C" void kernel_launch(void* const* d_in, const int* in_sizes, int n_in,
                              void* d_out, int out_size) {
    (void)in_sizes; (void)n_in; (void)out_size;
    cudaFuncSetAttribute(ipb_kernel, cudaFuncAttributeMaxDynamicSharedMemorySize, SM_BYTES);
    ipb_kernel<<<8192, TPB, SM_BYTES>>>(
        (const float*)d_in[0],   // x
        (const float*)d_in[1],   // W_qk
        (const float*)d_in[2],   // W_v
        (const float*)d_in[3],   // W_out
        (const float*)d_in[4],   // b_out
        (const float*)d_in[5],   // W_pcq
        (const float*)d_in[6],   // b_pcq
        (const float*)d_in[7],   // W_pck
        (const float*)d_in[8],   // b_pck
        (const float*)d_in[9],   // W_m1
        (const float*)d_in[10],  // W_m2a
        (const float*)d_in[11],  // W_m2b
        (float*)d_out);
}

// round 3
// speedup vs baseline: 1.8005x; 1.4120x over previous
#include <cuda_runtime.h>

// ---------------------------------------------------------------------------
// IPB windowed inhibition attention, fp32.
// Round 3: bytes/FMA-optimized smem pipeline. 8x4 tiles, W_out folded into V
// (out = attn @ (x (W_out W_v)^T) + b), transposed+swizzled attn buffer.
// One CTA per (window, B): 8192 CTAs x 256 threads.
// ---------------------------------------------------------------------------

#define TPB 256

namespace {
constexpr int H_STR = 256 * 28;        // 7168
constexpr int B_STR = 256 * 256 * 28;  // 1835008
constexpr int ST = 68;                 // padded stride (17 banks/row -> conflict-free cols)

// region A (5712 floats): sxT/sqT/skT, later aliased by attnT [64][68]
constexpr int OFF_XT  = 0;             // [28][68]
constexpr int OFF_QT  = 1904;          // [28][68]
constexpr int OFF_KT  = 3808;          // [28][68]
constexpr int OFF_AT  = 0;             // attnT [64][68] alias (needs 4352 <= 5712)
constexpr int OFF_WT  = 5712;          // [28][96]: cols 0..55 = W_qk^T, 56..83 = W_vo^T
constexpr int OFF_WV  = 8400;          // W_v  [28][28] row-major
constexpr int OFF_WO  = 9184;          // W_out[28][28] row-major
constexpr int OFF_V   = 9968;          // V' [64][28] row-major
constexpr int OFF_SIM = 11760;         // sim [64][68]
constexpr int OFF_SGQ = 16112;
constexpr int OFF_SGK = 16176;
constexpr int OFF_TH  = 16240;
constexpr int OFF_RED = 16304;
constexpr int SM_FLOATS = 16308;
constexpr int SM_BYTES  = SM_FLOATS * 4;   // 65232 B -> 3 CTAs/SM
}

__global__ void __launch_bounds__(TPB, 3) ipb_kernel(
    const float* __restrict__ x,
    const float* __restrict__ W_qk,   // [56,28]
    const float* __restrict__ W_v,    // [28,28]
    const float* __restrict__ W_out,  // [28,28]
    const float* __restrict__ b_out,  // [28]
    const float* __restrict__ W_pcq,  // [1,28]
    const float* __restrict__ b_pcq,  // [1]
    const float* __restrict__ W_pck,  // [1,28]
    const float* __restrict__ b_pck,  // [1]
    const float* __restrict__ W_m1,   // [1,64]
    const float* __restrict__ W_m2a,  // [64,64]
    const float* __restrict__ W_m2b,  // [1,64]
    float* __restrict__ out)
{
    extern __shared__ float sm[];
    float* sxT  = sm + OFF_XT;
    float* sqT  = sm + OFF_QT;
    float* skT  = sm + OFF_KT;
    float* satT = sm + OFF_AT;
    float* sWT  = sm + OFF_WT;
    float* sWv  = sm + OFF_WV;
    float* sWo  = sm + OFF_WO;
    float* sv   = sm + OFF_V;
    float* ssim = sm + OFF_SIM;
    float* sigq = sm + OFF_SGQ;
    float* sigk = sm + OFF_SGK;
    float* sth  = sm + OFF_TH;
    float* sred = sm + OFF_RED;

    const int tid  = threadIdx.x;
    const int widx = blockIdx.x & 1023;
    const int Bi   = blockIdx.x >> 10;
    const int wh = widx >> 5, ww = widx & 31;
    const float* xbase = x + (size_t)Bi * B_STR + wh * 8 * H_STR + ww * 8 * 28;

    // ======== S0: loads ========
    // x -> sxT transposed [28][68]. i: r = i&63 (token), c4 = (i>>6)*4.
    for (int i = tid; i < 448; i += TPB) {
        const int r = i & 63, c4 = (i >> 6) * 4;
        const float4 v = *(const float4*)(xbase + (r >> 3) * H_STR + (r & 7) * 28 + c4);
        sxT[(c4 + 0) * ST + r] = v.x;
        sxT[(c4 + 1) * ST + r] = v.y;
        sxT[(c4 + 2) * ST + r] = v.z;
        sxT[(c4 + 3) * ST + r] = v.w;
    }
    // W_qk -> sWT[k][c], c in 0..55. i: c = i%56, k4 = (i/56)*4.
    for (int i = tid; i < 392; i += TPB) {
        const int c = i % 56, k4 = (i / 56) * 4;
        const float4 v = *(const float4*)(W_qk + c * 28 + k4);
        sWT[(k4 + 0) * 96 + c] = v.x;
        sWT[(k4 + 1) * 96 + c] = v.y;
        sWT[(k4 + 2) * 96 + c] = v.z;
        sWT[(k4 + 3) * 96 + c] = v.w;
    }
    for (int i = tid; i < 196; i += TPB) {
        ((float4*)sWv)[i] = ((const float4*)W_v)[i];
        ((float4*)sWo)[i] = ((const float4*)W_out)[i];
    }
    __syncthreads();

    // ======== S0.5: W_vo = W_out @ W_v, store transposed into sWT cols 56..83 ====
    if (tid < 196) {
        const int c = tid / 7, e4 = (tid % 7) * 4;
        float4 acc = {0.f, 0.f, 0.f, 0.f};
        #pragma unroll 7
        for (int d = 0; d < 28; d++) {
            const float wc = sWo[c * 28 + d];
            const float4 wv = *(const float4*)&sWv[d * 28 + e4];
            acc.x = fmaf(wc, wv.x, acc.x); acc.y = fmaf(wc, wv.y, acc.y);
            acc.z = fmaf(wc, wv.z, acc.z); acc.w = fmaf(wc, wv.w, acc.w);
        }
        sWT[(e4 + 0) * 96 + 56 + c] = acc.x;
        sWT[(e4 + 1) * 96 + 56 + c] = acc.y;
        sWT[(e4 + 2) * 96 + 56 + c] = acc.z;
        sWT[(e4 + 3) * 96 + 56 + c] = acc.w;
    }
    __syncthreads();

    // ======== S1: [Q|K|V'] = x @ [W_qk | W_vo]^T, 8 tokens x 4 cols tiles ====
    if (tid < 168) {
        int t8, c4;
        const bool isQK = tid < 112;
        if (isQK) { t8 = (tid & 7) * 8;        c4 = (tid >> 3) * 4; }       // c4 0..52
        else      { const int v = tid - 112; c4 = (v % 7) * 4; t8 = (v / 7) * 8; }
        const int wcol = isQK ? c4 : (56 + c4);
        float4 accA[4] = {{0,0,0,0},{0,0,0,0},{0,0,0,0},{0,0,0,0}};  // tokens t8..t8+3 per col mm
        float4 accB[4] = {{0,0,0,0},{0,0,0,0},{0,0,0,0},{0,0,0,0}};  // tokens t8+4..t8+7
        #pragma unroll 4
        for (int k = 0; k < 28; k++) {
            const float4 a0 = *(const float4*)&sxT[k * ST + t8];
            const float4 a1 = *(const float4*)&sxT[k * ST + t8 + 4];
            const float4 w  = *(const float4*)&sWT[k * 96 + wcol];
            const float wm[4] = {w.x, w.y, w.z, w.w};
            #pragma unroll
            for (int mm = 0; mm < 4; mm++) {
                accA[mm].x = fmaf(a0.x, wm[mm], accA[mm].x);
                accA[mm].y = fmaf(a0.y, wm[mm], accA[mm].y);
                accA[mm].z = fmaf(a0.z, wm[mm], accA[mm].z);
                accA[mm].w = fmaf(a0.w, wm[mm], accA[mm].w);
                accB[mm].x = fmaf(a1.x, wm[mm], accB[mm].x);
                accB[mm].y = fmaf(a1.y, wm[mm], accB[mm].y);
                accB[mm].z = fmaf(a1.z, wm[mm], accB[mm].z);
                accB[mm].w = fmaf(a1.w, wm[mm], accB[mm].w);
            }
        }
        if (isQK) {
            float* dst = (c4 < 28) ? sqT : skT;
            const int cb = (c4 < 28) ? c4 : c4 - 28;
            #pragma unroll
            for (int mm = 0; mm < 4; mm++) {
                *(float4*)&dst[(cb + mm) * ST + t8]     = accA[mm];
                *(float4*)&dst[(cb + mm) * ST + t8 + 4] = accB[mm];
            }
        } else {
            // V' row-major [64][28]
            #pragma unroll
            for (int tt = 0; tt < 4; tt++) {
                *(float4*)&sv[(t8 + tt) * 28 + c4] =
                    make_float4(((const float*)&accA[0])[tt], ((const float*)&accA[1])[tt],
                                ((const float*)&accA[2])[tt], ((const float*)&accA[3])[tt]);
                *(float4*)&sv[(t8 + 4 + tt) * 28 + c4] =
                    make_float4(((const float*)&accB[0])[tt], ((const float*)&accB[1])[tt],
                                ((const float*)&accB[2])[tt], ((const float*)&accB[3])[tt]);
            }
        }
    }
    __syncthreads();

    // ======== S2: sigma (threads 128..255) + sim = Q K^T (threads 0..127) ====
    if (tid >= 128) {
        const int id = tid - 128;
        const int i = id & 63;
        const float* T  = (id < 64) ? sqT : skT;
        const float* wp = (id < 64) ? W_pcq : W_pck;
        float acc = (id < 64) ? b_pcq[0] : b_pck[0];
        #pragma unroll 7
        for (int c = 0; c < 28; c++) acc = fmaf(T[c * ST + i], wp[c], acc);
        ((id < 64) ? sigq : sigk)[i] = acc;
    } else {
        const int t8 = (tid >> 4) * 8;
        const int j4 = (tid & 15) * 4;
        float4 acc[8] = {{0,0,0,0},{0,0,0,0},{0,0,0,0},{0,0,0,0},
                         {0,0,0,0},{0,0,0,0},{0,0,0,0},{0,0,0,0}};
        #pragma unroll 4
        for (int k = 0; k < 28; k++) {
            const float4 q0 = *(const float4*)&sqT[k * ST + t8];
            const float4 q1 = *(const float4*)&sqT[k * ST + t8 + 4];
            const float4 kk = *(const float4*)&skT[k * ST + j4];
            const float qs[8] = {q0.x, q0.y, q0.z, q0.w, q1.x, q1.y, q1.z, q1.w};
            #pragma unroll
            for (int tt = 0; tt < 8; tt++) {
                acc[tt].x = fmaf(qs[tt], kk.x, acc[tt].x);
                acc[tt].y = fmaf(qs[tt], kk.y, acc[tt].y);
                acc[tt].z = fmaf(qs[tt], kk.z, acc[tt].z);
                acc[tt].w = fmaf(qs[tt], kk.w, acc[tt].w);
            }
        }
        #pragma unroll
        for (int tt = 0; tt < 8; tt++)
            *(float4*)&ssim[(t8 + tt) * ST + j4] = acc[tt];
    }
    __syncthreads();

    // ======== S3: theta_raw[i] = sum_{j!=i} sim[i,j] * W_m1[j] ========
    if (tid < 64) {
        const float* srow = ssim + tid * ST;
        float acc = 0.f;
        #pragma unroll
        for (int j4 = 0; j4 < 64; j4 += 4) {
            const float4 s = *(const float4*)&srow[j4];
            const float4 w = *(const float4*)&W_m1[j4];
            acc = fmaf(s.x, w.x, acc); acc = fmaf(s.y, w.y, acc);
            acc = fmaf(s.z, w.z, acc); acc = fmaf(s.w, w.w, acc);
        }
        acc -= srow[tid] * W_m1[tid];
        sth[tid] = acc;
    }
    __syncthreads();

    // ======== S4: theta = W_m2b . LeakyReLU(W_m2a @ theta_raw) ========
    if (tid < 64) {
        const float* wrow = W_m2a + tid * 64;
        float acc = 0.f;
        #pragma unroll
        for (int j4 = 0; j4 < 64; j4 += 4) {
            const float4 t = *(const float4*)&sth[j4];
            const float4 w = *(const float4*)&wrow[j4];
            acc = fmaf(t.x, w.x, acc); acc = fmaf(t.y, w.y, acc);
            acc = fmaf(t.z, w.z, acc); acc = fmaf(t.w, w.w, acc);
        }
        acc = (acc >= 0.f) ? acc : 0.1f * acc;
        float val = acc * W_m2b[tid];
        #pragma unroll
        for (int o = 16; o > 0; o >>= 1)
            val += __shfl_down_sync(0xffffffffu, val, o);
        if ((tid & 31) == 0) sred[tid >> 5] = val;
    }
    __syncthreads();
    const float theta = sred[0] + sred[1];

    // ======== S5: Sigma scale, softmax, threshold; write attn TRANSPOSED ====
    // attnT[j][t] stored at j*ST + 8*((t>>3)^(j>>3)) + (t&7)  (conflict-free)
    {
        const int lane = tid & 31, wrp = tid >> 5;
        #pragma unroll
        for (int it = 0; it < 8; it++) {
            const int r = it * 8 + wrp;
            const float* srow = ssim + r * ST;
            const float sgq = sigq[r];
            const float s0 = srow[lane]      * (sgq * sigk[lane]);
            const float s1 = srow[lane + 32] * (sgq * sigk[lane + 32]);
            float m = fmaxf(s0, s1);
            #pragma unroll
            for (int o = 16; o > 0; o >>= 1)
                m = fmaxf(m, __shfl_xor_sync(0xffffffffu, m, o));
            const float e0 = __expf(s0 - m), e1 = __expf(s1 - m);
            float ss = e0 + e1;
            #pragma unroll
            for (int o = 16; o > 0; o >>= 1)
                ss += __shfl_xor_sync(0xffffffffu, ss, o);
            const float inv = 1.0f / ss;
            const float a0 = (s0 > theta) ? e0 * inv : 0.f;
            const float a1 = (s1 > theta) ? e1 * inv : 0.f;
            const int ra = r >> 3, rb = r & 7;
            satT[lane * ST        + 8 * (ra ^ (lane >> 3))       + rb] = a0;
            satT[(lane + 32) * ST + 8 * (ra ^ ((lane >> 3) + 4)) + rb] = a1;
        }
    }
    __syncthreads();

    // ======== S6: out = attn @ V' + b_out (direct to gmem), 4t x 4d tiles ====
    if (tid < 112) {
        const int d4 = (tid % 7) * 4;
        const int t4 = (tid / 7) * 4;
        const int ta = t4 >> 3, tb = t4 & 7;   // chunk id + offset within chunk
        float4 acc[4] = {{0,0,0,0},{0,0,0,0},{0,0,0,0},{0,0,0,0}};
        #pragma unroll 4
        for (int j = 0; j < 64; j++) {
            const float4 at = *(const float4*)&satT[j * ST + 8 * (ta ^ (j >> 3)) + tb];
            const float4 vv = *(const float4*)&sv[j * 28 + d4];
            const float as[4] = {at.x, at.y, at.z, at.w};
            #pragma unroll
            for (int tt = 0; tt < 4; tt++) {
                acc[tt].x = fmaf(as[tt], vv.x, acc[tt].x);
                acc[tt].y = fmaf(as[tt], vv.y, acc[tt].y);
                acc[tt].z = fmaf(as[tt], vv.z, acc[tt].z);
                acc[tt].w = fmaf(as[tt], vv.w, acc[tt].w);
            }
        }
        const float4 bb = *(const float4*)&b_out[d4];
        #pragma unroll
        for (int tt = 0; tt < 4; tt++) {
            const int t = t4 + tt;
            float* ob = out + (size_t)Bi * B_STR + (wh * 8 + (t >> 3)) * H_STR
                        + (ww * 8 + (t & 7)) * 28 + d4;
            *(float4*)ob = make_float4(acc[tt].x + bb.x, acc[tt].y + bb.y,
                                       acc[tt].z + bb.z, acc[tt].w + bb.w);
        }
    }
}

extern "C" void kernel_launch(void* const* d_in, const int* in_sizes, int n_in,
                              void* d_out, int out_size) {
    (void)in_sizes; (void)n_in; (void)out_size;
    cudaFuncSetAttribute(ipb_kernel, cudaFuncAttributeMaxDynamicSharedMemorySize, SM_BYTES);
    ipb_kernel<<<8192, TPB, SM_BYTES>>>(
        (const float*)d_in[0],   // x
        (const float*)d_in[1],   // W_qk
        (const float*)d_in[2],   // W_v
        (const float*)d_in[3],   // W_out
        (const float*)d_in[4],   // b_out
        (const float*)d_in[5],   // W_pcq
        (const float*)d_in[6],   // b_pcq
        (const float*)d_in[7],   // W_pck
        (const float*)d_in[8],   // b_pck
        (const float*)d_in[9],   // W_m1
        (const float*)d_in[10],  // W_m2a
        (const float*)d_in[11],  // W_m2b
        (float*)d_out);
}